// round 13
// baseline (speedup 1.0000x reference)
#include <cuda_runtime.h>
#include <math.h>

// Problem constants (fixed by reference setup_inputs)
#define BB    512
#define KK    8
#define PP    6
#define DD    1024
#define NIDS  64
#define NGRP  (2 * NIDS)
#define MARGIN 0.2f
#define GRID  (BB * PP)           // 6144-block grid uses one block per (b,p)

// Scratch (no allocations allowed)
__device__ float g_w[BB];         // fused per-sample weight (1/(grp*K*P*denom))
__device__ float g_cinv[BB];      // 1/max(cnt_cross,1)
__device__ int   g_boff[BB];      // CSR offset of sample b's CROSS group
__device__ int   g_bcnt[BB];      // count of sample b's CROSS group
__device__ int   g_list[BB];      // CSR sample indices grouped by (mod,id)

// ---------------------------------------------------------------------------
// K1: one block, 512 threads. Histogram, validity, id_count, parallel
//     exclusive scan (shfl), fused weights, CSR lists, zero d_out.
// ---------------------------------------------------------------------------
__global__ void k1_setup(const int* __restrict__ pids,
                         const int* __restrict__ camids,
                         float* __restrict__ out) {
    __shared__ int scnt[NGRP];
    __shared__ int scur[NGRP];
    __shared__ int soff[NGRP];        // exclusive prefix of scnt
    __shared__ int svalid[NIDS];
    __shared__ int s_idcount;
    __shared__ int warpsum[4];

    int t = threadIdx.x;
    if (t < NGRP) { scnt[t] = 0; scur[t] = 0; }
    if (t == 0) s_idcount = 0;
    __syncthreads();

    int pid = 0, cam = 0, own_grp = 0;
    if (t < BB) {
        pid = pids[t];
        cam = camids[t];
        int mod = (cam == 0) ? 0 : 1;
        own_grp = mod * NIDS + pid;
        atomicAdd(&scnt[own_grp], 1);
    }
    __syncthreads();

    if (t < NIDS) {
        int v = (scnt[t] > 0 && scnt[NIDS + t] > 0) ? 1 : 0;
        svalid[t] = v;
        if (v) atomicAdd(&s_idcount, 1);
    }

    // Parallel exclusive scan of scnt[0..127] using first 4 warps
    int v = 0, inc = 0;
    if (t < NGRP) {
        v = scnt[t];
        inc = v;
        int lane = t & 31;
#pragma unroll
        for (int d = 1; d < 32; d <<= 1) {
            int n = __shfl_up_sync(0xffffffffu, inc, d);
            if (lane >= d) inc += n;
        }
        if (lane == 31) warpsum[t >> 5] = inc;
    }
    __syncthreads();
    if (t == 0) {
        int a = 0;
#pragma unroll
        for (int i = 0; i < 4; ++i) { int x = warpsum[i]; warpsum[i] = a; a += x; }
    }
    __syncthreads();
    if (t < NGRP) soff[t] = inc - v + warpsum[t >> 5];   // exclusive prefix
    __syncthreads();

    float denom = fmaxf((float)s_idcount, 1.0f);

    if (t < BB) {
        int rgb = (cam == 0);
        int cross_grp = (rgb ? 1 : 0) * NIDS + pid;
        float grp_cnt = fmaxf((float)scnt[own_grp], 1.0f);
        float w = svalid[pid] ? (1.0f / (grp_cnt * (float)KK * (float)PP * denom)) : 0.0f;
        g_w[t] = w;
        g_cinv[t] = 1.0f / fmaxf((float)scnt[cross_grp], 1.0f);
        g_boff[t] = soff[cross_grp];
        g_bcnt[t] = scnt[cross_grp];
        int pos = atomicAdd(&scur[own_grp], 1);
        g_list[soff[own_grp] + pos] = t;
    }
    if (t == 0) out[0] = 0.0f;
}

// ---------------------------------------------------------------------------
// K4: 128-thread block per (b,p). 4 warps x 2 k-rows. Stage own row
//     (independent of k1), griddepcontrol.wait, CSR gather, stream.
// ---------------------------------------------------------------------------
__global__ void __launch_bounds__(128) k4_main(const float* __restrict__ f_orig,
                                               const float* __restrict__ f_gen,
                                               float* __restrict__ out) {
    __shared__ float so[DD];          // own f_original row     4 KB
    __shared__ float sc[DD];          // cross-center row       4 KB
    __shared__ float spart[4];

    int bp = blockIdx.x;              // 0 .. GRID-1
    int b = bp / PP;
    int p = bp - b * PP;
    int t = threadIdx.x;              // 128 threads; owns float4 #t and #t+128
    int w = t >> 5;                   // 0..3
    int lane = t & 31;

    const float4* fo4 = reinterpret_cast<const float4*>(f_orig);
    float4* so4 = reinterpret_cast<float4*>(so);
    float4* sc4 = reinterpret_cast<float4*>(sc);

    // Stage own row — independent of k1, overlaps with k1 completion
    size_t orow = ((size_t)(b * PP + p) * DD) >> 2;
    so4[t]       = fo4[orow + t];
    so4[t + 128] = fo4[orow + t + 128];

    // Wait for k1's outputs (PDL sync point)
    asm volatile("griddepcontrol.wait;" ::: "memory");

    // Gather cross-center row over CSR member list (both halves per member)
    int off = g_boff[b];
    int cnt = g_bcnt[b];
    float cinv = g_cinv[b];
    float4 a0 = make_float4(0.f, 0.f, 0.f, 0.f);
    float4 a1 = make_float4(0.f, 0.f, 0.f, 0.f);
    int j = 0;
    for (; j + 2 <= cnt; j += 2) {
        size_t m0 = (((size_t)(g_list[off + j + 0] * PP + p) * DD) >> 2);
        size_t m1 = (((size_t)(g_list[off + j + 1] * PP + p) * DD) >> 2);
        float4 v0 = fo4[m0 + t];
        float4 v1 = fo4[m0 + t + 128];
        float4 v2 = fo4[m1 + t];
        float4 v3 = fo4[m1 + t + 128];
        a0.x += v0.x + v2.x; a0.y += v0.y + v2.y;
        a0.z += v0.z + v2.z; a0.w += v0.w + v2.w;
        a1.x += v1.x + v3.x; a1.y += v1.y + v3.y;
        a1.z += v1.z + v3.z; a1.w += v1.w + v3.w;
    }
    if (j < cnt) {
        size_t m0 = (((size_t)(g_list[off + j] * PP + p) * DD) >> 2);
        float4 v0 = fo4[m0 + t];
        float4 v1 = fo4[m0 + t + 128];
        a0.x += v0.x; a0.y += v0.y; a0.z += v0.z; a0.w += v0.w;
        a1.x += v1.x; a1.y += v1.y; a1.z += v1.z; a1.w += v1.w;
    }
    a0.x *= cinv; a0.y *= cinv; a0.z *= cinv; a0.w *= cinv;
    a1.x *= cinv; a1.y *= cinv; a1.z *= cinv; a1.w *= cinv;
    sc4[t]       = a0;
    sc4[t + 128] = a1;
    __syncthreads();

    // Main stream: warp w handles k-rows w and w+4
    float hsum = 0.0f;
#pragma unroll
    for (int rr = 0; rr < 2; ++rr) {
        int k = w + rr * 4;
        const float4* gp = reinterpret_cast<const float4*>(
            f_gen + ((size_t)((b * KK + k) * PP + p)) * DD);

        float4 g[8];
#pragma unroll
        for (int it = 0; it < 8; ++it) g[it] = gp[it * 32 + lane];

        float s_pull = 0.0f, s_push = 0.0f;
#pragma unroll
        for (int it = 0; it < 8; ++it) {
            float4 o = so4[it * 32 + lane];
            float4 c = sc4[it * 32 + lane];
            float dx, dy, dz, dw;
            dx = g[it].x - c.x; dy = g[it].y - c.y;
            dz = g[it].z - c.z; dw = g[it].w - c.w;
            s_pull += dx * dx + dy * dy + dz * dz + dw * dw;
            dx = g[it].x - o.x; dy = g[it].y - o.y;
            dz = g[it].z - o.z; dw = g[it].w - o.w;
            s_push += dx * dx + dy * dy + dz * dz + dw * dw;
        }
#pragma unroll
        for (int s = 16; s; s >>= 1) {
            s_pull += __shfl_down_sync(0xffffffffu, s_pull, s);
            s_push += __shfl_down_sync(0xffffffffu, s_push, s);
        }
        if (lane == 0) {
            float h = sqrtf(s_pull) - sqrtf(s_push) + MARGIN;
            hsum += fmaxf(h, 0.0f);
        }
    }

    if (lane == 0) spart[w] = hsum;
    __syncthreads();
    if (t == 0) {
        float s = (spart[0] + spart[1]) + (spart[2] + spart[3]);
        atomicAdd(out, s * g_w[b]);
    }
}

// ---------------------------------------------------------------------------
extern "C" void kernel_launch(void* const* d_in, const int* in_sizes, int n_in,
                              void* d_out, int out_size) {
    const float* f_orig = (const float*)d_in[0];
    const float* f_gen  = (const float*)d_in[1];
    const int*   pids   = (const int*)d_in[2];
    const int*   camids = (const int*)d_in[3];
    float*       out    = (float*)d_out;

    k1_setup<<<1, 512>>>(pids, camids, out);

    // PDL: let k4 launch before k1 completes; k4 syncs via griddepcontrol.wait
    cudaLaunchConfig_t cfg = {};
    cfg.gridDim  = dim3(GRID);
    cfg.blockDim = dim3(128);
    cfg.dynamicSmemBytes = 0;
    cfg.stream = 0;
    cudaLaunchAttribute attrs[1];
    attrs[0].id = cudaLaunchAttributeProgrammaticStreamSerialization;
    attrs[0].val.programmaticStreamSerializationAllowed = 1;
    cfg.attrs = attrs;
    cfg.numAttrs = 1;
    cudaLaunchKernelEx(&cfg, k4_main, f_orig, f_gen, out);
}

// round 14
// speedup vs baseline: 1.0376x; 1.0376x over previous
#include <cuda_runtime.h>
#include <math.h>

// Problem constants (fixed by reference setup_inputs)
#define BB    512
#define KK    8
#define PP    6
#define DD    1024
#define NIDS  64
#define NGRP  (2 * NIDS)
#define MARGIN 0.2f
#define GRID  (BB * PP)           // 3072 blocks, one per (b,p)

// Scratch (no allocations allowed)
__device__ float g_w[BB];         // fused per-sample weight (1/(grp*K*P*denom))
__device__ float g_cinv[BB];      // 1/max(cnt_cross,1)
__device__ int   g_boff[BB];      // CSR offset of sample b's CROSS group
__device__ int   g_bcnt[BB];      // count of sample b's CROSS group
__device__ int   g_list[BB];      // CSR sample indices grouped by (mod,id)

// ---------------------------------------------------------------------------
// K1: one block, 512 threads. Histogram, validity, id_count, parallel
//     exclusive scan (shfl), fused weights, CSR lists, zero d_out.
// ---------------------------------------------------------------------------
__global__ void k1_setup(const int* __restrict__ pids,
                         const int* __restrict__ camids,
                         float* __restrict__ out) {
    __shared__ int scnt[NGRP];
    __shared__ int scur[NGRP];
    __shared__ int soff[NGRP];        // exclusive prefix of scnt
    __shared__ int svalid[NIDS];
    __shared__ int s_idcount;
    __shared__ int warpsum[4];

    int t = threadIdx.x;
    if (t < NGRP) { scnt[t] = 0; scur[t] = 0; }
    if (t == 0) s_idcount = 0;
    __syncthreads();

    int pid = 0, cam = 0, own_grp = 0;
    if (t < BB) {
        pid = pids[t];
        cam = camids[t];
        int mod = (cam == 0) ? 0 : 1;
        own_grp = mod * NIDS + pid;
        atomicAdd(&scnt[own_grp], 1);
    }
    __syncthreads();

    if (t < NIDS) {
        int v = (scnt[t] > 0 && scnt[NIDS + t] > 0) ? 1 : 0;
        svalid[t] = v;
        if (v) atomicAdd(&s_idcount, 1);
    }

    // Parallel exclusive scan of scnt[0..127] using first 4 warps
    int v = 0, inc = 0;
    if (t < NGRP) {
        v = scnt[t];
        inc = v;
        int lane = t & 31;
#pragma unroll
        for (int d = 1; d < 32; d <<= 1) {
            int n = __shfl_up_sync(0xffffffffu, inc, d);
            if (lane >= d) inc += n;
        }
        if (lane == 31) warpsum[t >> 5] = inc;
    }
    __syncthreads();
    if (t == 0) {
        int a = 0;
#pragma unroll
        for (int i = 0; i < 4; ++i) { int x = warpsum[i]; warpsum[i] = a; a += x; }
    }
    __syncthreads();
    if (t < NGRP) soff[t] = inc - v + warpsum[t >> 5];   // exclusive prefix
    __syncthreads();

    float denom = fmaxf((float)s_idcount, 1.0f);

    if (t < BB) {
        int rgb = (cam == 0);
        int cross_grp = (rgb ? 1 : 0) * NIDS + pid;
        float grp_cnt = fmaxf((float)scnt[own_grp], 1.0f);
        float w = svalid[pid] ? (1.0f / (grp_cnt * (float)KK * (float)PP * denom)) : 0.0f;
        g_w[t] = w;
        g_cinv[t] = 1.0f / fmaxf((float)scnt[cross_grp], 1.0f);
        g_boff[t] = soff[cross_grp];
        g_bcnt[t] = scnt[cross_grp];
        int pos = atomicAdd(&scur[own_grp], 1);
        g_list[soff[own_grp] + pos] = t;
    }
    if (t == 0) out[0] = 0.0f;
}

// ---------------------------------------------------------------------------
// K4 (R12 shape, reg-capped for 8 blocks/SM): one block per (b,p). Stage own
//     row (independent of k1), griddepcontrol.wait, CSR gather, then 8 warps
//     each stream one k-row of f_gen with 8 batched float4 loads.
// ---------------------------------------------------------------------------
__global__ void __launch_bounds__(256, 8) k4_main(const float* __restrict__ f_orig,
                                                  const float* __restrict__ f_gen,
                                                  float* __restrict__ out) {
    __shared__ float so[DD];          // own f_original row
    __shared__ float sc[DD];          // cross-modality center row
    __shared__ float spart[8];

    int bp = blockIdx.x;              // 0 .. GRID-1
    int b = bp / PP;
    int p = bp - b * PP;
    int t = threadIdx.x;              // 256 threads; thread t owns float4 #t
    int w = t >> 5;
    int lane = t & 31;

    const float4* fo4 = reinterpret_cast<const float4*>(f_orig);
    float4* so4 = reinterpret_cast<float4*>(so);
    float4* sc4 = reinterpret_cast<float4*>(sc);

    // Stage own row — independent of k1, overlaps with k1 completion
    so4[t] = fo4[(((size_t)(b * PP + p) * DD) >> 2) + t];

    // Wait for k1's outputs to be visible (PDL sync point)
    asm volatile("griddepcontrol.wait;" ::: "memory");

    // Gather cross-center row over CSR member list
    int off = g_boff[b];
    int cnt = g_bcnt[b];
    float cinv = g_cinv[b];
    float4 acc = make_float4(0.f, 0.f, 0.f, 0.f);
    int j = 0;
    for (; j + 4 <= cnt; j += 4) {
        int b0 = g_list[off + j + 0], b1 = g_list[off + j + 1];
        int b2 = g_list[off + j + 2], b3 = g_list[off + j + 3];
        float4 v0 = fo4[(((size_t)(b0 * PP + p) * DD) >> 2) + t];
        float4 v1 = fo4[(((size_t)(b1 * PP + p) * DD) >> 2) + t];
        float4 v2 = fo4[(((size_t)(b2 * PP + p) * DD) >> 2) + t];
        float4 v3 = fo4[(((size_t)(b3 * PP + p) * DD) >> 2) + t];
        acc.x += (v0.x + v1.x) + (v2.x + v3.x);
        acc.y += (v0.y + v1.y) + (v2.y + v3.y);
        acc.z += (v0.z + v1.z) + (v2.z + v3.z);
        acc.w += (v0.w + v1.w) + (v2.w + v3.w);
    }
    for (; j < cnt; ++j) {
        int bs = g_list[off + j];
        float4 vv = fo4[(((size_t)(bs * PP + p) * DD) >> 2) + t];
        acc.x += vv.x; acc.y += vv.y; acc.z += vv.z; acc.w += vv.w;
    }
    acc.x *= cinv; acc.y *= cinv; acc.z *= cinv; acc.w *= cinv;
    sc4[t] = acc;
    __syncthreads();

    // Main stream: warp w handles f_generated[b, w, p, :]
    const float4* gp = reinterpret_cast<const float4*>(
        f_gen + ((size_t)((b * KK + w) * PP + p)) * DD);

    float4 g[8];
#pragma unroll
    for (int it = 0; it < 8; ++it) g[it] = gp[it * 32 + lane];

    float s_pull = 0.0f, s_push = 0.0f;
#pragma unroll
    for (int it = 0; it < 8; ++it) {
        float4 o = so4[it * 32 + lane];
        float4 c = sc4[it * 32 + lane];
        float dx, dy, dz, dw;
        dx = g[it].x - c.x; dy = g[it].y - c.y;
        dz = g[it].z - c.z; dw = g[it].w - c.w;
        s_pull += dx * dx + dy * dy + dz * dz + dw * dw;
        dx = g[it].x - o.x; dy = g[it].y - o.y;
        dz = g[it].z - o.z; dw = g[it].w - o.w;
        s_push += dx * dx + dy * dy + dz * dz + dw * dw;
    }
#pragma unroll
    for (int s = 16; s; s >>= 1) {
        s_pull += __shfl_down_sync(0xffffffffu, s_pull, s);
        s_push += __shfl_down_sync(0xffffffffu, s_push, s);
    }
    if (lane == 0) {
        float h = sqrtf(s_pull) - sqrtf(s_push) + MARGIN;
        spart[w] = fmaxf(h, 0.0f);
    }
    __syncthreads();
    if (t == 0) {
        float s = 0.0f;
#pragma unroll
        for (int i = 0; i < 8; ++i) s += spart[i];
        atomicAdd(out, s * g_w[b]);
    }
}

// ---------------------------------------------------------------------------
extern "C" void kernel_launch(void* const* d_in, const int* in_sizes, int n_in,
                              void* d_out, int out_size) {
    const float* f_orig = (const float*)d_in[0];
    const float* f_gen  = (const float*)d_in[1];
    const int*   pids   = (const int*)d_in[2];
    const int*   camids = (const int*)d_in[3];
    float*       out    = (float*)d_out;

    k1_setup<<<1, 512>>>(pids, camids, out);

    // PDL: let k4 launch before k1 completes; k4 syncs via griddepcontrol.wait
    cudaLaunchConfig_t cfg = {};
    cfg.gridDim  = dim3(GRID);
    cfg.blockDim = dim3(256);
    cfg.dynamicSmemBytes = 0;
    cfg.stream = 0;
    cudaLaunchAttribute attrs[1];
    attrs[0].id = cudaLaunchAttributeProgrammaticStreamSerialization;
    attrs[0].val.programmaticStreamSerializationAllowed = 1;
    cfg.attrs = attrs;
    cfg.numAttrs = 1;
    cudaLaunchKernelEx(&cfg, k4_main, f_orig, f_gen, out);
}

// round 16
// speedup vs baseline: 1.1514x; 1.1097x over previous
#include <cuda_runtime.h>
#include <math.h>

// Problem constants (fixed by reference setup_inputs)
#define BB    512
#define KK    8
#define PP    6
#define DD    1024
#define NIDS  64
#define NGRP  (2 * NIDS)
#define MARGIN 0.2f
#define GRID  (BB * PP)           // 3072 blocks, one per (b,p)

// Scratch (no allocations allowed)
__device__ float g_w[BB];         // fused per-sample weight (1/(grp*K*P*denom))
__device__ float g_cinv[BB];      // 1/max(cnt_cross,1)
__device__ int   g_boff[BB];      // CSR offset of sample b's CROSS group
__device__ int   g_bcnt[BB];      // count of sample b's CROSS group
__device__ int   g_list[BB];      // CSR sample indices grouped by (mod,id)

// Portable warp-wide float sum (butterfly).
__device__ __forceinline__ float warp_sum(float v) {
#pragma unroll
    for (int s = 16; s; s >>= 1) v += __shfl_xor_sync(0xffffffffu, v, s);
    return v;
}

// ---------------------------------------------------------------------------
// K1: one block, 512 threads. Histogram, validity, id_count, parallel
//     exclusive scan (shfl), fused weights, CSR lists, zero d_out.
// ---------------------------------------------------------------------------
__global__ void k1_setup(const int* __restrict__ pids,
                         const int* __restrict__ camids,
                         float* __restrict__ out) {
    __shared__ int scnt[NGRP];
    __shared__ int scur[NGRP];
    __shared__ int soff[NGRP];        // exclusive prefix of scnt
    __shared__ int svalid[NIDS];
    __shared__ int s_idcount;
    __shared__ int warpsum[4];

    int t = threadIdx.x;
    if (t < NGRP) { scnt[t] = 0; scur[t] = 0; }
    if (t == 0) s_idcount = 0;
    __syncthreads();

    int pid = 0, cam = 0, own_grp = 0;
    if (t < BB) {
        pid = pids[t];
        cam = camids[t];
        int mod = (cam == 0) ? 0 : 1;
        own_grp = mod * NIDS + pid;
        atomicAdd(&scnt[own_grp], 1);
    }
    __syncthreads();

    if (t < NIDS) {
        int v = (scnt[t] > 0 && scnt[NIDS + t] > 0) ? 1 : 0;
        svalid[t] = v;
        if (v) atomicAdd(&s_idcount, 1);
    }

    // Parallel exclusive scan of scnt[0..127] using first 4 warps
    int v = 0, inc = 0;
    if (t < NGRP) {
        v = scnt[t];
        inc = v;
        int lane = t & 31;
#pragma unroll
        for (int d = 1; d < 32; d <<= 1) {
            int n = __shfl_up_sync(0xffffffffu, inc, d);
            if (lane >= d) inc += n;
        }
        if (lane == 31) warpsum[t >> 5] = inc;
    }
    __syncthreads();
    if (t == 0) {
        int a = 0;
#pragma unroll
        for (int i = 0; i < 4; ++i) { int x = warpsum[i]; warpsum[i] = a; a += x; }
    }
    __syncthreads();
    if (t < NGRP) soff[t] = inc - v + warpsum[t >> 5];   // exclusive prefix
    __syncthreads();

    float denom = fmaxf((float)s_idcount, 1.0f);

    if (t < BB) {
        int rgb = (cam == 0);
        int cross_grp = (rgb ? 1 : 0) * NIDS + pid;
        float grp_cnt = fmaxf((float)scnt[own_grp], 1.0f);
        float w = svalid[pid] ? (1.0f / (grp_cnt * (float)KK * (float)PP * denom)) : 0.0f;
        g_w[t] = w;
        g_cinv[t] = 1.0f / fmaxf((float)scnt[cross_grp], 1.0f);
        g_boff[t] = soff[cross_grp];
        g_bcnt[t] = scnt[cross_grp];
        int pos = atomicAdd(&scur[own_grp], 1);
        g_list[soff[own_grp] + pos] = t;
    }
    if (t == 0) out[0] = 0.0f;
}

// ---------------------------------------------------------------------------
// K4 (R12 shape + __ldcs stream): one block per (b,p). Stage own row
//     (independent of k1), griddepcontrol.wait, CSR gather, then 8 warps
//     each stream one k-row of f_gen with 8 batched evict-first float4 loads.
// ---------------------------------------------------------------------------
__global__ void __launch_bounds__(256) k4_main(const float* __restrict__ f_orig,
                                               const float* __restrict__ f_gen,
                                               float* __restrict__ out) {
    __shared__ float so[DD];          // own f_original row
    __shared__ float sc[DD];          // cross-modality center row
    __shared__ float spart[8];

    int bp = blockIdx.x;              // 0 .. GRID-1
    int b = bp / PP;
    int p = bp - b * PP;
    int t = threadIdx.x;              // 256 threads; thread t owns float4 #t
    int w = t >> 5;
    int lane = t & 31;

    const float4* fo4 = reinterpret_cast<const float4*>(f_orig);
    float4* so4 = reinterpret_cast<float4*>(so);
    float4* sc4 = reinterpret_cast<float4*>(sc);

    // Stage own row — independent of k1, overlaps with k1 completion
    so4[t] = fo4[(((size_t)(b * PP + p) * DD) >> 2) + t];

    // Wait for k1's outputs to be visible (PDL sync point)
    asm volatile("griddepcontrol.wait;" ::: "memory");

    // Gather cross-center row over CSR member list
    int off = g_boff[b];
    int cnt = g_bcnt[b];
    float cinv = g_cinv[b];
    float4 acc = make_float4(0.f, 0.f, 0.f, 0.f);
    int j = 0;
    for (; j + 4 <= cnt; j += 4) {
        int b0 = g_list[off + j + 0], b1 = g_list[off + j + 1];
        int b2 = g_list[off + j + 2], b3 = g_list[off + j + 3];
        float4 v0 = fo4[(((size_t)(b0 * PP + p) * DD) >> 2) + t];
        float4 v1 = fo4[(((size_t)(b1 * PP + p) * DD) >> 2) + t];
        float4 v2 = fo4[(((size_t)(b2 * PP + p) * DD) >> 2) + t];
        float4 v3 = fo4[(((size_t)(b3 * PP + p) * DD) >> 2) + t];
        acc.x += (v0.x + v1.x) + (v2.x + v3.x);
        acc.y += (v0.y + v1.y) + (v2.y + v3.y);
        acc.z += (v0.z + v1.z) + (v2.z + v3.z);
        acc.w += (v0.w + v1.w) + (v2.w + v3.w);
    }
    for (; j < cnt; ++j) {
        int bs = g_list[off + j];
        float4 vv = fo4[(((size_t)(bs * PP + p) * DD) >> 2) + t];
        acc.x += vv.x; acc.y += vv.y; acc.z += vv.z; acc.w += vv.w;
    }
    acc.x *= cinv; acc.y *= cinv; acc.z *= cinv; acc.w *= cinv;
    sc4[t] = acc;
    __syncthreads();

    // Main stream: warp w handles f_generated[b, w, p, :] (evict-first)
    const float4* gp = reinterpret_cast<const float4*>(
        f_gen + ((size_t)((b * KK + w) * PP + p)) * DD);

    float4 g[8];
#pragma unroll
    for (int it = 0; it < 8; ++it) g[it] = __ldcs(&gp[it * 32 + lane]);

    float s_pull = 0.0f, s_push = 0.0f;
#pragma unroll
    for (int it = 0; it < 8; ++it) {
        float4 o = so4[it * 32 + lane];
        float4 c = sc4[it * 32 + lane];
        float dx, dy, dz, dw;
        dx = g[it].x - c.x; dy = g[it].y - c.y;
        dz = g[it].z - c.z; dw = g[it].w - c.w;
        s_pull += dx * dx + dy * dy + dz * dz + dw * dw;
        dx = g[it].x - o.x; dy = g[it].y - o.y;
        dz = g[it].z - o.z; dw = g[it].w - o.w;
        s_push += dx * dx + dy * dy + dz * dz + dw * dw;
    }

    s_pull = warp_sum(s_pull);
    s_push = warp_sum(s_push);

    if (lane == 0) {
        float h = sqrtf(s_pull) - sqrtf(s_push) + MARGIN;
        spart[w] = fmaxf(h, 0.0f);
    }
    __syncthreads();
    if (t == 0) {
        float s = 0.0f;
#pragma unroll
        for (int i = 0; i < 8; ++i) s += spart[i];
        atomicAdd(out, s * g_w[b]);
    }
}

// ---------------------------------------------------------------------------
extern "C" void kernel_launch(void* const* d_in, const int* in_sizes, int n_in,
                              void* d_out, int out_size) {
    const float* f_orig = (const float*)d_in[0];
    const float* f_gen  = (const float*)d_in[1];
    const int*   pids   = (const int*)d_in[2];
    const int*   camids = (const int*)d_in[3];
    float*       out    = (float*)d_out;

    k1_setup<<<1, 512>>>(pids, camids, out);

    // PDL: let k4 launch before k1 completes; k4 syncs via griddepcontrol.wait
    cudaLaunchConfig_t cfg = {};
    cfg.gridDim  = dim3(GRID);
    cfg.blockDim = dim3(256);
    cfg.dynamicSmemBytes = 0;
    cfg.stream = 0;
    cudaLaunchAttribute attrs[1];
    attrs[0].id = cudaLaunchAttributeProgrammaticStreamSerialization;
    attrs[0].val.programmaticStreamSerializationAllowed = 1;
    cfg.attrs = attrs;
    cfg.numAttrs = 1;
    cudaLaunchKernelEx(&cfg, k4_main, f_orig, f_gen, out);
}